// round 6
// baseline (speedup 1.0000x reference)
#include <cuda_runtime.h>
#include <cuda_bf16.h>
#include <cstddef>
#include <cstdint>

// Problem constants
#define B_   2
#define S_   2048
#define DM_  1024
#define H_   16
#define DK_  64
#define M_   (B_ * S_)             // 4096 rows
#define OUT_ELEMS  ((long long)M_ * DM_)                 // 4,194,304
#define ATTN_ELEMS ((long long)B_ * H_ * S_ * S_)        // 134,217,728
#define KB_  16                    // 2048/128 k-blocks per row

// ---------------- scratch (device globals) ----------------
__device__ float g_Q[M_ * DM_];
__device__ float g_K[M_ * DM_];
__device__ float g_V[M_ * DM_];
__device__ float g_ctx[M_ * DM_];
__device__ float g_y[M_ * DM_];
__device__ float g_attn[(size_t)B_ * H_ * S_ * S_];      // raw scores scratch
__device__ float2 g_stats[(size_t)B_ * H_ * S_ * KB_];   // per (bh,q,kblock): {m, sigma}
__device__ float2 g_rowstats[(size_t)B_ * H_ * S_];      // per (bh,q): {m, 1/S}
__device__ int   g_maskmode;   // 0=uint8, 1=int32, 2=float32

// =====================================================================
// Fast exp via exp2 poly (FMA pipe, no MUFU). Rel err ~1e-7.
// Underflows to exactly 0 for x < ~-87 (handles -1e9 masked scores).
// =====================================================================
__device__ __forceinline__ float fexp(float x)
{
    float t = x * 1.442695041f;
    if (t < -126.0f) return 0.0f;
    float fi = floorf(t);
    float f  = t - fi;
    float p  = 1.8775767e-3f;
    p = fmaf(p, f, 8.9893397e-3f);
    p = fmaf(p, f, 5.5826318e-2f);
    p = fmaf(p, f, 2.4015361e-1f);
    p = fmaf(p, f, 6.9315308e-1f);
    p = fmaf(p, f, 1.0f);
    return p * __int_as_float(((int)fi + 127) << 23);
}

// =====================================================================
// Mask storage-format detection (proven)
// =====================================================================
__global__ void detect_mask_kernel(const unsigned char* __restrict__ m)
{
    __shared__ int cnt[4];
    if (threadIdx.x < 4) cnt[threadIdx.x] = 0;
    __syncthreads();
    for (int i = threadIdx.x; i < 65536; i += blockDim.x)
        if (m[i]) atomicAdd(&cnt[i & 3], 1);
    __syncthreads();
    if (threadIdx.x == 0) {
        int mode;
        if (cnt[1] > 0)      mode = 0;
        else if (cnt[0] > 0) mode = 1;
        else                 mode = 2;
        g_maskmode = mode;
    }
}

// =====================================================================
// mma.sync helpers
// =====================================================================
__device__ __forceinline__ void ldsm_x4(uint32_t* r, uint32_t addr) {
    asm volatile("ldmatrix.sync.aligned.m8n8.x4.shared.b16 {%0,%1,%2,%3}, [%4];"
                 : "=r"(r[0]), "=r"(r[1]), "=r"(r[2]), "=r"(r[3]) : "r"(addr));
}
__device__ __forceinline__ void ldsm_x4t(uint32_t* r, uint32_t addr) {
    asm volatile("ldmatrix.sync.aligned.m8n8.x4.trans.shared.b16 {%0,%1,%2,%3}, [%4];"
                 : "=r"(r[0]), "=r"(r[1]), "=r"(r[2]), "=r"(r[3]) : "r"(addr));
}
__device__ __forceinline__ void mma_bf16(float* c, const uint32_t* a, const uint32_t* b) {
    asm volatile(
        "mma.sync.aligned.m16n8k16.row.col.f32.bf16.bf16.f32 "
        "{%0,%1,%2,%3}, {%4,%5,%6,%7}, {%8,%9}, {%0,%1,%2,%3};"
        : "+f"(c[0]), "+f"(c[1]), "+f"(c[2]), "+f"(c[3])
        : "r"(a[0]), "r"(a[1]), "r"(a[2]), "r"(a[3]), "r"(b[0]), "r"(b[1]));
}

__device__ __forceinline__ void split_bf16(float x, __nv_bfloat16& h, __nv_bfloat16& l) {
    h = __float2bfloat16_rn(x);
    l = __float2bfloat16_rn(x - __bfloat162float(h));
}

// =====================================================================
// Generalized mma.sync split-bf16 GEMM.
//   IS_CTX=false:  C[4096,1024] = A[4096,1024]@B[1024,1024] (+Res)
//   IS_CTX=true :  per bh: ctx[2048,64] = softmax(scores)[2048,2048]@V[2048,64]
//     A holds RAW scores; p = fexp(s - m)*invS applied inline using rowstats;
//     normalized p is also written to attn_out (the attn output tensor).
// Block tile 128(M)x64(N), 8 warps (4x2), warp tile 32x32, K-chunk 64.
// =====================================================================
#define PADK 72
#define SM_AH 0
#define SM_AL (128 * PADK * 2)
#define SM_BH (2 * 128 * PADK * 2)
#define SM_BL (2 * 128 * PADK * 2 + 64 * PADK * 2)
#define MMA_SMEM_BYTES (2 * 128 * PADK * 2 + 2 * 64 * PADK * 2)   // 55296
#define SM_RS MMA_SMEM_BYTES
#define CTX_SMEM_BYTES (MMA_SMEM_BYTES + 128 * 8)                  // + rowstats

template<bool IS_CTX>
__global__ __launch_bounds__(256) void mma_gemm_t(
    const float* __restrict__ A, const float* __restrict__ Bm,
    const float* __restrict__ Res, float* __restrict__ C,
    const float2* __restrict__ rowstats, float* __restrict__ attn_out)
{
    extern __shared__ __align__(16) char dsm[];
    const uint32_t sbase = (uint32_t)__cvta_generic_to_shared(dsm);

    const int tid  = threadIdx.x;
    const int lane = tid & 31;
    const int warp = tid >> 5;
    const int wm   = warp & 3;
    const int wn   = warp >> 2;
    const int row0 = blockIdx.y * 128;
    const int n0   = blockIdx.x * 64;

    int lda, ldb, ldc, kLen;
    float2* sm_rs = (float2*)(dsm + SM_RS);
    if (IS_CTX) {
        const int bh = blockIdx.z;
        const int b  = bh >> 4;
        const int h  = bh & 15;
        A += (size_t)bh * S_ * S_;
        attn_out += (size_t)bh * S_ * S_;
        Bm += (size_t)b * S_ * DM_ + h * DK_;
        C += (size_t)b * S_ * DM_ + h * DK_;
        lda = S_; ldb = DM_; ldc = DM_; kLen = S_;
        if (tid < 128) sm_rs[tid] = rowstats[(size_t)bh * S_ + row0 + tid];
        __syncthreads();
    } else {
        lda = DM_; ldb = DM_; ldc = DM_; kLen = DM_;
    }

    float acc[2][4][4];
#pragma unroll
    for (int i = 0; i < 2; i++)
#pragma unroll
        for (int j = 0; j < 4; j++)
#pragma unroll
            for (int k = 0; k < 4; k++) acc[i][j][k] = 0.f;

    uint32_t aoff[2], boff[2];
#pragma unroll
    for (int mi = 0; mi < 2; ++mi)
        aoff[mi] = (uint32_t)((wm * 32 + mi * 16 + (lane & 15)) * PADK + (lane >> 4) * 8);
#pragma unroll
    for (int njp = 0; njp < 2; ++njp)
        boff[njp] = (uint32_t)((((lane >> 3) & 1) * 8 + (lane & 7)) * PADK
                               + wn * 32 + njp * 16 + (lane >> 4) * 8);

    for (int c = 0; c < kLen / 64; ++c) {
        const int k0 = c * 64;

        float4 av[8];
#pragma unroll
        for (int i = 0; i < 8; ++i) {
            int idx = tid + i * 256;
            int r  = idx >> 4;
            int kc = (idx & 15) * 4;
            av[i] = *(const float4*)&A[(size_t)(row0 + r) * lda + k0 + kc];
        }
        if (IS_CTX) {
            // softmax finalize: p = fexp(s - m) * invS; write attn output
#pragma unroll
            for (int i = 0; i < 8; ++i) {
                int idx = tid + i * 256;
                int r  = idx >> 4;
                int kc = (idx & 15) * 4;
                float2 st = sm_rs[r];
                float4 pv;
                pv.x = fexp(av[i].x - st.x) * st.y;
                pv.y = fexp(av[i].y - st.x) * st.y;
                pv.z = fexp(av[i].z - st.x) * st.y;
                pv.w = fexp(av[i].w - st.x) * st.y;
                *(float4*)&attn_out[(size_t)(row0 + r) * lda + k0 + kc] = pv;
                av[i] = pv;
            }
        }
        float4 bv[4];
#pragma unroll
        for (int i = 0; i < 4; ++i) {
            int idx = tid + i * 256;
            int kr = idx >> 4;
            int nc = (idx & 15) * 4;
            bv[i] = *(const float4*)&Bm[(size_t)(k0 + kr) * ldb + n0 + nc];
        }

        if (c > 0) __syncthreads();

#pragma unroll
        for (int i = 0; i < 8; ++i) {
            int idx = tid + i * 256;
            int r  = idx >> 4;
            int kc = (idx & 15) * 4;
            uint32_t eo = (uint32_t)(r * PADK + kc) * 2;
            __nv_bfloat16 h0, h1, h2, h3, l0, l1, l2, l3;
            split_bf16(av[i].x, h0, l0); split_bf16(av[i].y, h1, l1);
            split_bf16(av[i].z, h2, l2); split_bf16(av[i].w, h3, l3);
            *(__nv_bfloat162*)(dsm + SM_AH + eo)     = __halves2bfloat162(h0, h1);
            *(__nv_bfloat162*)(dsm + SM_AH + eo + 4) = __halves2bfloat162(h2, h3);
            *(__nv_bfloat162*)(dsm + SM_AL + eo)     = __halves2bfloat162(l0, l1);
            *(__nv_bfloat162*)(dsm + SM_AL + eo + 4) = __halves2bfloat162(l2, l3);
        }
#pragma unroll
        for (int i = 0; i < 4; ++i) {
            int idx = tid + i * 256;
            int kr = idx >> 4;
            int nc = (idx & 15) * 4;
            uint32_t eo = (uint32_t)(kr * PADK + nc) * 2;
            __nv_bfloat16 h0, h1, h2, h3, l0, l1, l2, l3;
            split_bf16(bv[i].x, h0, l0); split_bf16(bv[i].y, h1, l1);
            split_bf16(bv[i].z, h2, l2); split_bf16(bv[i].w, h3, l3);
            *(__nv_bfloat162*)(dsm + SM_BH + eo)     = __halves2bfloat162(h0, h1);
            *(__nv_bfloat162*)(dsm + SM_BH + eo + 4) = __halves2bfloat162(h2, h3);
            *(__nv_bfloat162*)(dsm + SM_BL + eo)     = __halves2bfloat162(l0, l1);
            *(__nv_bfloat162*)(dsm + SM_BL + eo + 4) = __halves2bfloat162(l2, l3);
        }
        __syncthreads();

#pragma unroll
        for (int ks = 0; ks < 4; ++ks) {
            uint32_t ah[2][4], al[2][4], bh[2][4], bl[2][4];
#pragma unroll
            for (int mi = 0; mi < 2; ++mi) {
                uint32_t eo = (aoff[mi] + ks * 16) * 2;
                ldsm_x4(ah[mi], sbase + SM_AH + eo);
                ldsm_x4(al[mi], sbase + SM_AL + eo);
            }
#pragma unroll
            for (int njp = 0; njp < 2; ++njp) {
                uint32_t eo = (boff[njp] + ks * 16 * PADK) * 2;
                ldsm_x4t(bh[njp], sbase + SM_BH + eo);
                ldsm_x4t(bl[njp], sbase + SM_BL + eo);
            }
#pragma unroll
            for (int mi = 0; mi < 2; ++mi) {
#pragma unroll
                for (int nj = 0; nj < 4; ++nj) {
                    const uint32_t* bhp = &bh[nj >> 1][(nj & 1) * 2];
                    const uint32_t* blp = &bl[nj >> 1][(nj & 1) * 2];
                    mma_bf16(acc[mi][nj], ah[mi], bhp);
                    mma_bf16(acc[mi][nj], ah[mi], blp);
                    mma_bf16(acc[mi][nj], al[mi], bhp);
                }
            }
        }
    }

#pragma unroll
    for (int mi = 0; mi < 2; ++mi) {
#pragma unroll
        for (int nj = 0; nj < 4; ++nj) {
            int rg = row0 + wm * 32 + mi * 16 + (lane >> 2);
            int cg = n0 + wn * 32 + nj * 8 + (lane & 3) * 2;
            float2 v0 = make_float2(acc[mi][nj][0], acc[mi][nj][1]);
            float2 v1 = make_float2(acc[mi][nj][2], acc[mi][nj][3]);
            if (Res) {
                float2 r0 = *(const float2*)&Res[(size_t)rg * ldc + cg];
                float2 r1 = *(const float2*)&Res[(size_t)(rg + 8) * ldc + cg];
                v0.x += r0.x; v0.y += r0.y;
                v1.x += r1.x; v1.y += r1.y;
            }
            *(float2*)&C[(size_t)rg * ldc + cg]       = v0;
            *(float2*)&C[(size_t)(rg + 8) * ldc + cg] = v1;
        }
    }
}

// =====================================================================
// Scores via mma.sync split-bf16 + online softmax block-stats.
//   scores[bh,q,k] = masked ? -1e9 : (Q_h q . K_h k) / 8   (raw, to scratch)
//   stats[bh,q,kb] = {m_b = max over 128 cols, sigma_b = sum fexp(s - m_b)}
// Block tile 128q x 128k, 8 warps (4x2), warp 32q x 64k, d=64 resident.
// =====================================================================
#define SC_QH 0
#define SC_QL (128 * PADK * 2)
#define SC_KH (2 * 128 * PADK * 2)
#define SC_KL (3 * 128 * PADK * 2)
#define SC_RED (4 * 128 * PADK * 2)
#define SC_SMEM_BYTES (4 * 128 * PADK * 2 + 2 * 2 * 128 * 4)   // 75776

__global__ __launch_bounds__(256) void scores_mma(
    const float* __restrict__ Q, const float* __restrict__ Kp,
    const unsigned char* __restrict__ mask_u8, float* __restrict__ scores,
    float2* __restrict__ stats)
{
    extern __shared__ __align__(16) char dsm[];
    const uint32_t sbase = (uint32_t)__cvta_generic_to_shared(dsm);

    const int bh = blockIdx.z;
    const int b  = bh >> 4;
    const int h  = bh & 15;
    const int q0 = blockIdx.y * 128;
    const int k0 = blockIdx.x * 128;
    const int kb = blockIdx.x;
    const int tid  = threadIdx.x;
    const int lane = tid & 31;
    const int warp = tid >> 5;
    const int wm   = warp & 3;    // q: 4 x 32
    const int wn   = warp >> 2;   // k: 2 x 64
    const int mode = g_maskmode;

    // ---- load Q/K tiles (128 rows x 64 d fp32), split to hi/lo bf16 ----
    float4 qv[8], kv[8];
#pragma unroll
    for (int i = 0; i < 8; ++i) {
        int idx = tid + i * 256;
        int r  = idx >> 4;
        int d4 = (idx & 15) * 4;
        qv[i] = *(const float4*)&Q[((size_t)(b * S_ + q0 + r)) * DM_ + h * DK_ + d4];
        kv[i] = *(const float4*)&Kp[((size_t)(b * S_ + k0 + r)) * DM_ + h * DK_ + d4];
    }
#pragma unroll
    for (int i = 0; i < 8; ++i) {
        int idx = tid + i * 256;
        int r  = idx >> 4;
        int d4 = (idx & 15) * 4;
        uint32_t eo = (uint32_t)(r * PADK + d4) * 2;
        __nv_bfloat16 h0, h1, h2, h3, l0, l1, l2, l3;
        split_bf16(qv[i].x, h0, l0); split_bf16(qv[i].y, h1, l1);
        split_bf16(qv[i].z, h2, l2); split_bf16(qv[i].w, h3, l3);
        *(__nv_bfloat162*)(dsm + SC_QH + eo)     = __halves2bfloat162(h0, h1);
        *(__nv_bfloat162*)(dsm + SC_QH + eo + 4) = __halves2bfloat162(h2, h3);
        *(__nv_bfloat162*)(dsm + SC_QL + eo)     = __halves2bfloat162(l0, l1);
        *(__nv_bfloat162*)(dsm + SC_QL + eo + 4) = __halves2bfloat162(l2, l3);
        split_bf16(kv[i].x, h0, l0); split_bf16(kv[i].y, h1, l1);
        split_bf16(kv[i].z, h2, l2); split_bf16(kv[i].w, h3, l3);
        *(__nv_bfloat162*)(dsm + SC_KH + eo)     = __halves2bfloat162(h0, h1);
        *(__nv_bfloat162*)(dsm + SC_KH + eo + 4) = __halves2bfloat162(h2, h3);
        *(__nv_bfloat162*)(dsm + SC_KL + eo)     = __halves2bfloat162(l0, l1);
        *(__nv_bfloat162*)(dsm + SC_KL + eo + 4) = __halves2bfloat162(l2, l3);
    }
    __syncthreads();

    float acc[2][8][4];
#pragma unroll
    for (int i = 0; i < 2; i++)
#pragma unroll
        for (int j = 0; j < 8; j++)
#pragma unroll
            for (int k = 0; k < 4; k++) acc[i][j][k] = 0.f;

    uint32_t aoff[2];
#pragma unroll
    for (int mi = 0; mi < 2; ++mi)
        aoff[mi] = (uint32_t)((wm * 32 + mi * 16 + (lane & 15)) * PADK + (lane >> 4) * 8);
    const uint32_t bbase = (uint32_t)((wn * 64 + (lane >> 4) * 8 + (lane & 7)) * PADK
                                      + ((lane >> 3) & 1) * 8);

#pragma unroll
    for (int ks = 0; ks < 4; ++ks) {
        uint32_t ah[2][4], al[2][4], bh[4][4], bl[4][4];
#pragma unroll
        for (int mi = 0; mi < 2; ++mi) {
            uint32_t eo = (aoff[mi] + ks * 16) * 2;
            ldsm_x4(ah[mi], sbase + SC_QH + eo);
            ldsm_x4(al[mi], sbase + SC_QL + eo);
        }
#pragma unroll
        for (int j = 0; j < 4; ++j) {
            uint32_t eo = (bbase + j * 16 * PADK + ks * 16) * 2;
            ldsm_x4(bh[j], sbase + SC_KH + eo);
            ldsm_x4(bl[j], sbase + SC_KL + eo);
        }
#pragma unroll
        for (int mi = 0; mi < 2; ++mi) {
#pragma unroll
            for (int nj = 0; nj < 8; ++nj) {
                const uint32_t* bhp = &bh[nj >> 1][(nj & 1) * 2];
                const uint32_t* blp = &bl[nj >> 1][(nj & 1) * 2];
                mma_bf16(acc[mi][nj], ah[mi], bhp);
                mma_bf16(acc[mi][nj], ah[mi], blp);
                mma_bf16(acc[mi][nj], al[mi], bhp);
            }
        }
    }

    // ---- epilogue: scale 1/8, mask -> acc (masked values), write scores ----
    const int*   mask_i32 = (const int*)mask_u8;
    const float* mask_f32 = (const float*)mask_u8;
#pragma unroll
    for (int mi = 0; mi < 2; ++mi) {
#pragma unroll
        for (int nj = 0; nj < 8; ++nj) {
            int qg = q0 + wm * 32 + mi * 16 + (lane >> 2);
            int kg = k0 + wn * 64 + nj * 8 + (lane & 3) * 2;
#pragma unroll
            for (int rr = 0; rr < 2; ++rr) {
                int qr = qg + rr * 8;
                float s0 = acc[mi][nj][rr * 2 + 0] * 0.125f;
                float s1 = acc[mi][nj][rr * 2 + 1] * 0.125f;
                size_t midx = ((size_t)b * S_ + qr) * S_ + kg;
                bool m0, m1;
                if (mode == 1) {
                    int2 mv = *(const int2*)&mask_i32[midx];
                    m0 = mv.x != 0; m1 = mv.y != 0;
                } else if (mode == 0) {
                    m0 = mask_u8[midx] != 0; m1 = mask_u8[midx + 1] != 0;
                } else {
                    float2 mv = *(const float2*)&mask_f32[midx];
                    m0 = mv.x != 0.0f; m1 = mv.y != 0.0f;
                }
                float v0 = m0 ? -1e9f : s0;
                float v1 = m1 ? -1e9f : s1;
                acc[mi][nj][rr * 2 + 0] = v0;
                acc[mi][nj][rr * 2 + 1] = v1;
                *(float2*)&scores[((size_t)bh * S_ + qr) * S_ + kg] = make_float2(v0, v1);
            }
        }
    }

    // ---- block softmax stats: per-row max + sum of fexp(s - m_b) ----
    float* sm_m = (float*)(dsm + SC_RED);   // [2][128]
    float* sm_s = sm_m + 256;               // [2][128]

    float mx[2][2];
#pragma unroll
    for (int mi = 0; mi < 2; ++mi)
#pragma unroll
        for (int rr = 0; rr < 2; ++rr) {
            float m = -3.4e38f;
#pragma unroll
            for (int nj = 0; nj < 8; ++nj) {
                m = fmaxf(m, acc[mi][nj][rr * 2 + 0]);
                m = fmaxf(m, acc[mi][nj][rr * 2 + 1]);
            }
            m = fmaxf(m, __shfl_xor_sync(0xffffffffu, m, 1));
            m = fmaxf(m, __shfl_xor_sync(0xffffffffu, m, 2));
            mx[mi][rr] = m;
        }
    if ((lane & 3) == 0) {
#pragma unroll
        for (int mi = 0; mi < 2; ++mi)
#pragma unroll
            for (int rr = 0; rr < 2; ++rr)
                sm_m[wn * 128 + wm * 32 + mi * 16 + rr * 8 + (lane >> 2)] = mx[mi][rr];
    }
    __syncthreads();

    float sg[2][2];
#pragma unroll
    for (int mi = 0; mi < 2; ++mi)
#pragma unroll
        for (int rr = 0; rr < 2; ++rr) {
            int row = wm * 32 + mi * 16 + rr * 8 + (lane >> 2);
            float mb = fmaxf(sm_m[row], sm_m[128 + row]);
            float s = 0.f;
#pragma unroll
            for (int nj = 0; nj < 8; ++nj) {
                s += fexp(acc[mi][nj][rr * 2 + 0] - mb);
                s += fexp(acc[mi][nj][rr * 2 + 1] - mb);
            }
            s += __shfl_xor_sync(0xffffffffu, s, 1);
            s += __shfl_xor_sync(0xffffffffu, s, 2);
            sg[mi][rr] = s;
        }
    if ((lane & 3) == 0) {
#pragma unroll
        for (int mi = 0; mi < 2; ++mi)
#pragma unroll
            for (int rr = 0; rr < 2; ++rr)
                sm_s[wn * 128 + wm * 32 + mi * 16 + rr * 8 + (lane >> 2)] = sg[mi][rr];
    }
    __syncthreads();

    if (tid < 128) {
        float mb  = fmaxf(sm_m[tid], sm_m[128 + tid]);
        float sig = sm_s[tid] + sm_s[128 + tid];
        stats[((size_t)bh * S_ + q0 + tid) * KB_ + kb] = make_float2(mb, sig);
    }
}

// =====================================================================
// Combine per-kblock stats into per-row {m, 1/S}
// =====================================================================
__global__ __launch_bounds__(256) void reduce_stats(
    const float2* __restrict__ stats, float2* __restrict__ rowstats)
{
    int row = blockIdx.x * 256 + threadIdx.x;   // 0 .. 65535
    const float2* p = stats + (size_t)row * KB_;
    float2 v[KB_];
    float m = -3.4e38f;
#pragma unroll
    for (int i = 0; i < KB_; ++i) { v[i] = p[i]; m = fmaxf(m, v[i].x); }
    float S = 0.f;
#pragma unroll
    for (int i = 0; i < KB_; ++i) S += v[i].y * fexp(v[i].x - m);
    rowstats[row] = make_float2(m, 1.0f / S);
}

// =====================================================================
// LayerNorm (unchanged)
// =====================================================================
__global__ __launch_bounds__(256) void ln_kernel(
    const float* __restrict__ y, float* __restrict__ out)
{
    const int tid = threadIdx.x;
    const float* p = y + (size_t)blockIdx.x * DM_;
    float* o = out + (size_t)blockIdx.x * DM_;
    const int warp = tid >> 5, lane = tid & 31;
    __shared__ float red[8];

    float v[4];
#pragma unroll
    for (int j = 0; j < 4; j++) v[j] = p[tid + j * 256];

    float s = v[0] + v[1] + v[2] + v[3];
#pragma unroll
    for (int o2 = 16; o2 > 0; o2 >>= 1) s += __shfl_xor_sync(0xffffffffu, s, o2);
    if (lane == 0) red[warp] = s;
    __syncthreads();
    if (tid == 0) {
        float t = 0.f;
#pragma unroll
        for (int w = 0; w < 8; w++) t += red[w];
        red[0] = t;
    }
    __syncthreads();
    float mu = red[0] * (1.0f / DM_);

    float sq = 0.f;
#pragma unroll
    for (int j = 0; j < 4; j++) { float d = v[j] - mu; sq += d * d; }
#pragma unroll
    for (int o2 = 16; o2 > 0; o2 >>= 1) sq += __shfl_xor_sync(0xffffffffu, sq, o2);
    __syncthreads();
    if (lane == 0) red[warp] = sq;
    __syncthreads();
    if (tid == 0) {
        float t = 0.f;
#pragma unroll
        for (int w = 0; w < 8; w++) t += red[w];
        red[0] = t;
    }
    __syncthreads();
    float inv = rsqrtf(red[0] * (1.0f / DM_) + 1e-5f);

#pragma unroll
    for (int j = 0; j < 4; j++) o[tid + j * 256] = (v[j] - mu) * inv;
}

// =====================================================================
// Launch
// =====================================================================
extern "C" void kernel_launch(void* const* d_in, const int* in_sizes, int n_in,
                              void* d_out, int out_size)
{
    const float* inQ = (const float*)d_in[0];
    const float* inK = (const float*)d_in[1];
    const float* inV = (const float*)d_in[2];
    const unsigned char* mask = (const unsigned char*)d_in[3];
    const float* WQ = (const float*)d_in[4];
    const float* WK = (const float*)d_in[5];
    const float* WV = (const float*)d_in[6];
    const float* WO = (const float*)d_in[7];
    float* out = (float*)d_out;

    float *Qp, *Kp, *Vp, *Cp, *Yp, *Ap;
    float2 *Stp, *Rsp;
    cudaGetSymbolAddress((void**)&Qp, g_Q);
    cudaGetSymbolAddress((void**)&Kp, g_K);
    cudaGetSymbolAddress((void**)&Vp, g_V);
    cudaGetSymbolAddress((void**)&Cp, g_ctx);
    cudaGetSymbolAddress((void**)&Yp, g_y);
    cudaGetSymbolAddress((void**)&Ap, g_attn);
    cudaGetSymbolAddress((void**)&Stp, g_stats);
    cudaGetSymbolAddress((void**)&Rsp, g_rowstats);

    float* attn = ((long long)out_size >= OUT_ELEMS + ATTN_ELEMS) ? (out + OUT_ELEMS) : Ap;

    cudaFuncSetAttribute(mma_gemm_t<false>, cudaFuncAttributeMaxDynamicSharedMemorySize,
                         MMA_SMEM_BYTES);
    cudaFuncSetAttribute(mma_gemm_t<true>, cudaFuncAttributeMaxDynamicSharedMemorySize,
                         CTX_SMEM_BYTES);
    cudaFuncSetAttribute(scores_mma, cudaFuncAttributeMaxDynamicSharedMemorySize,
                         SC_SMEM_BYTES);

    detect_mask_kernel<<<1, 256>>>(mask);

    dim3 proj_grid(DM_ / 64, M_ / 128);   // (16, 32)
    mma_gemm_t<false><<<proj_grid, 256, MMA_SMEM_BYTES>>>(inQ, WQ, nullptr, Qp, nullptr, nullptr);
    mma_gemm_t<false><<<proj_grid, 256, MMA_SMEM_BYTES>>>(inK, WK, nullptr, Kp, nullptr, nullptr);
    mma_gemm_t<false><<<proj_grid, 256, MMA_SMEM_BYTES>>>(inV, WV, nullptr, Vp, nullptr, nullptr);

    // raw masked scores -> scratch, plus per-kblock softmax stats
    scores_mma<<<dim3(S_ / 128, S_ / 128, B_ * H_), 256, SC_SMEM_BYTES>>>(Qp, Kp, mask, Ap, Stp);
    reduce_stats<<<(B_ * H_ * S_) / 256, 256>>>(Stp, Rsp);
    // fused softmax-finalize + attn write + ctx GEMM
    mma_gemm_t<true><<<dim3(1, S_ / 128, B_ * H_), 256, CTX_SMEM_BYTES>>>(Ap, Vp, nullptr, Cp, Rsp, attn);

    mma_gemm_t<false><<<proj_grid, 256, MMA_SMEM_BYTES>>>(Cp, WO, inQ, Yp, nullptr, nullptr);
    ln_kernel<<<M_, 256>>>(Yp, out);
}

// round 7
// speedup vs baseline: 1.0832x; 1.0832x over previous
#include <cuda_runtime.h>
#include <cuda_bf16.h>
#include <cstddef>
#include <cstdint>

// Problem constants
#define B_   2
#define S_   2048
#define DM_  1024
#define H_   16
#define DK_  64
#define M_   (B_ * S_)             // 4096 rows
#define OUT_ELEMS  ((long long)M_ * DM_)                 // 4,194,304
#define ATTN_ELEMS ((long long)B_ * H_ * S_ * S_)        // 134,217,728

// ---------------- scratch (device globals) ----------------
__device__ float g_y[M_ * DM_];
__device__ float g_attn[(size_t)B_ * H_ * S_ * S_];      // fallback attn
__device__ __nv_bfloat16 g_Ah[M_ * DM_], g_Al[M_ * DM_];         // gemm A / ctx out
__device__ __nv_bfloat16 g_Wh[DM_ * DM_], g_Wl[DM_ * DM_];       // weight (reused)
__device__ __nv_bfloat16 g_Qh[M_ * DM_], g_Ql[M_ * DM_];
__device__ __nv_bfloat16 g_Kh[M_ * DM_], g_Kl[M_ * DM_];
__device__ __nv_bfloat16 g_Vh[M_ * DM_], g_Vl[M_ * DM_];
__device__ int g_maskmode;   // 0=uint8, 1=int32, 2=float32

// =====================================================================
// Fast exp via exp2 poly (FMA pipe, no MUFU). Rel err ~1e-7.
// Underflows to exactly 0 for x < ~-87 (handles -1e9 masked scores).
// =====================================================================
__device__ __forceinline__ float fexp(float x)
{
    float t = x * 1.442695041f;
    if (t < -126.0f) return 0.0f;
    float fi = floorf(t);
    float f  = t - fi;
    float p  = 1.8775767e-3f;
    p = fmaf(p, f, 8.9893397e-3f);
    p = fmaf(p, f, 5.5826318e-2f);
    p = fmaf(p, f, 2.4015361e-1f);
    p = fmaf(p, f, 6.9315308e-1f);
    p = fmaf(p, f, 1.0f);
    return p * __int_as_float(((int)fi + 127) << 23);
}

// =====================================================================
// Mask storage-format detection (proven)
// =====================================================================
__global__ void detect_mask_kernel(const unsigned char* __restrict__ m)
{
    __shared__ int cnt[4];
    if (threadIdx.x < 4) cnt[threadIdx.x] = 0;
    __syncthreads();
    for (int i = threadIdx.x; i < 65536; i += blockDim.x)
        if (m[i]) atomicAdd(&cnt[i & 3], 1);
    __syncthreads();
    if (threadIdx.x == 0) {
        int mode;
        if (cnt[1] > 0)      mode = 0;
        else if (cnt[0] > 0) mode = 1;
        else                 mode = 2;
        g_maskmode = mode;
    }
}

// =====================================================================
// mma.sync helpers
// =====================================================================
__device__ __forceinline__ void ldsm_x4(uint32_t* r, uint32_t addr) {
    asm volatile("ldmatrix.sync.aligned.m8n8.x4.shared.b16 {%0,%1,%2,%3}, [%4];"
                 : "=r"(r[0]), "=r"(r[1]), "=r"(r[2]), "=r"(r[3]) : "r"(addr));
}
__device__ __forceinline__ void ldsm_x4t(uint32_t* r, uint32_t addr) {
    asm volatile("ldmatrix.sync.aligned.m8n8.x4.trans.shared.b16 {%0,%1,%2,%3}, [%4];"
                 : "=r"(r[0]), "=r"(r[1]), "=r"(r[2]), "=r"(r[3]) : "r"(addr));
}
__device__ __forceinline__ void mma_bf16(float* c, const uint32_t* a, const uint32_t* b) {
    asm volatile(
        "mma.sync.aligned.m16n8k16.row.col.f32.bf16.bf16.f32 "
        "{%0,%1,%2,%3}, {%4,%5,%6,%7}, {%8,%9}, {%0,%1,%2,%3};"
        : "+f"(c[0]), "+f"(c[1]), "+f"(c[2]), "+f"(c[3])
        : "r"(a[0]), "r"(a[1]), "r"(a[2]), "r"(a[3]), "r"(b[0]), "r"(b[1]));
}

__device__ __forceinline__ void split_bf16(float x, __nv_bfloat16& h, __nv_bfloat16& l) {
    h = __float2bfloat16_rn(x);
    l = __float2bfloat16_rn(x - __bfloat162float(h));
}

// =====================================================================
// fp32 -> (hi, lo) bf16 splitter. 8 elements per thread, uint4 stores.
// =====================================================================
__global__ __launch_bounds__(256) void conv_split(
    const float* __restrict__ src,
    __nv_bfloat16* __restrict__ hi, __nv_bfloat16* __restrict__ lo)
{
    int i = (blockIdx.x * 256 + threadIdx.x) * 8;
    float4 a = *(const float4*)&src[i];
    float4 b = *(const float4*)&src[i + 4];
    union { __nv_bfloat162 b2[4]; uint4 u; } uh, ul;
    __nv_bfloat16 h0, h1, l0, l1;
    split_bf16(a.x, h0, l0); split_bf16(a.y, h1, l1);
    uh.b2[0] = __halves2bfloat162(h0, h1); ul.b2[0] = __halves2bfloat162(l0, l1);
    split_bf16(a.z, h0, l0); split_bf16(a.w, h1, l1);
    uh.b2[1] = __halves2bfloat162(h0, h1); ul.b2[1] = __halves2bfloat162(l0, l1);
    split_bf16(b.x, h0, l0); split_bf16(b.y, h1, l1);
    uh.b2[2] = __halves2bfloat162(h0, h1); ul.b2[2] = __halves2bfloat162(l0, l1);
    split_bf16(b.z, h0, l0); split_bf16(b.w, h1, l1);
    uh.b2[3] = __halves2bfloat162(h0, h1); ul.b2[3] = __halves2bfloat162(l0, l1);
    *(uint4*)&hi[i] = uh.u;
    *(uint4*)&lo[i] = ul.u;
}

// =====================================================================
// Pre-split GEMM: C[4096,1024] = A@B, A/B as hi/lo bf16 in global.
// C = Ah*Bh + Ah*Bl + Al*Bh (fp32 accum).
// OUT_FP32: fp32 C (+Res).  else: C emitted as hi/lo bf16 pair.
// Block tile 128(M)x64(N), 8 warps (4x2), warp 32x32, K-chunk 64.
// =====================================================================
#define PADK 72
#define SM_AH 0
#define SM_AL (128 * PADK * 2)
#define SM_BH (2 * 128 * PADK * 2)
#define SM_BL (2 * 128 * PADK * 2 + 64 * PADK * 2)
#define MMA_SMEM_BYTES (2 * 128 * PADK * 2 + 2 * 64 * PADK * 2)   // 55296

template<bool OUT_FP32>
__global__ __launch_bounds__(256) void gemm_bf16(
    const __nv_bfloat16* __restrict__ Ah, const __nv_bfloat16* __restrict__ Al,
    const __nv_bfloat16* __restrict__ Bh, const __nv_bfloat16* __restrict__ Bl,
    const float* __restrict__ Res, float* __restrict__ Cf,
    __nv_bfloat16* __restrict__ Ch, __nv_bfloat16* __restrict__ Cl)
{
    extern __shared__ __align__(16) char dsm[];
    const uint32_t sbase = (uint32_t)__cvta_generic_to_shared(dsm);

    const int tid  = threadIdx.x;
    const int lane = tid & 31;
    const int warp = tid >> 5;
    const int wm   = warp & 3;
    const int wn   = warp >> 2;
    const int row0 = blockIdx.y * 128;
    const int n0   = blockIdx.x * 64;

    float acc[2][4][4];
#pragma unroll
    for (int i = 0; i < 2; i++)
#pragma unroll
        for (int j = 0; j < 4; j++)
#pragma unroll
            for (int k = 0; k < 4; k++) acc[i][j][k] = 0.f;

    uint32_t aoff[2], boff[2];
#pragma unroll
    for (int mi = 0; mi < 2; ++mi)
        aoff[mi] = (uint32_t)((wm * 32 + mi * 16 + (lane & 15)) * PADK + (lane >> 4) * 8);
#pragma unroll
    for (int njp = 0; njp < 2; ++njp)
        boff[njp] = (uint32_t)((((lane >> 3) & 1) * 8 + (lane & 7)) * PADK
                               + wn * 32 + njp * 16 + (lane >> 4) * 8);

    // per-thread tile coordinates for loads (8 bf16 = uint4 granules)
    const int ar = tid >> 3, ac8 = (tid & 7) * 8;          // A: +32 rows per i
    const int br = tid >> 3, bc8 = (tid & 7) * 8;          // B: +32 rows per i

    for (int c = 0; c < DM_ / 64; ++c) {
        const int k0 = c * 64;

        uint4 ah4[4], al4[4], bh4[2], bl4[2];
#pragma unroll
        for (int i = 0; i < 4; ++i) {
            size_t off = (size_t)(row0 + ar + i * 32) * DM_ + k0 + ac8;
            ah4[i] = *(const uint4*)&Ah[off];
            al4[i] = *(const uint4*)&Al[off];
        }
#pragma unroll
        for (int i = 0; i < 2; ++i) {
            size_t off = (size_t)(k0 + br + i * 32) * DM_ + n0 + bc8;
            bh4[i] = *(const uint4*)&Bh[off];
            bl4[i] = *(const uint4*)&Bl[off];
        }

        if (c > 0) __syncthreads();

#pragma unroll
        for (int i = 0; i < 4; ++i) {
            uint32_t eo = (uint32_t)((ar + i * 32) * PADK + ac8) * 2;
            *(uint4*)(dsm + SM_AH + eo) = ah4[i];
            *(uint4*)(dsm + SM_AL + eo) = al4[i];
        }
#pragma unroll
        for (int i = 0; i < 2; ++i) {
            uint32_t eo = (uint32_t)((br + i * 32) * PADK + bc8) * 2;
            *(uint4*)(dsm + SM_BH + eo) = bh4[i];
            *(uint4*)(dsm + SM_BL + eo) = bl4[i];
        }
        __syncthreads();

#pragma unroll
        for (int ks = 0; ks < 4; ++ks) {
            uint32_t ah[2][4], al[2][4], bh[2][4], bl[2][4];
#pragma unroll
            for (int mi = 0; mi < 2; ++mi) {
                uint32_t eo = (aoff[mi] + ks * 16) * 2;
                ldsm_x4(ah[mi], sbase + SM_AH + eo);
                ldsm_x4(al[mi], sbase + SM_AL + eo);
            }
#pragma unroll
            for (int njp = 0; njp < 2; ++njp) {
                uint32_t eo = (boff[njp] + ks * 16 * PADK) * 2;
                ldsm_x4t(bh[njp], sbase + SM_BH + eo);
                ldsm_x4t(bl[njp], sbase + SM_BL + eo);
            }
#pragma unroll
            for (int mi = 0; mi < 2; ++mi) {
#pragma unroll
                for (int nj = 0; nj < 4; ++nj) {
                    const uint32_t* bhp = &bh[nj >> 1][(nj & 1) * 2];
                    const uint32_t* blp = &bl[nj >> 1][(nj & 1) * 2];
                    mma_bf16(acc[mi][nj], ah[mi], bhp);
                    mma_bf16(acc[mi][nj], ah[mi], blp);
                    mma_bf16(acc[mi][nj], al[mi], bhp);
                }
            }
        }
    }

#pragma unroll
    for (int mi = 0; mi < 2; ++mi) {
#pragma unroll
        for (int nj = 0; nj < 4; ++nj) {
            int rg = row0 + wm * 32 + mi * 16 + (lane >> 2);
            int cg = n0 + wn * 32 + nj * 8 + (lane & 3) * 2;
#pragma unroll
            for (int rr = 0; rr < 2; ++rr) {
                int r = rg + rr * 8;
                float v0 = acc[mi][nj][rr * 2 + 0];
                float v1 = acc[mi][nj][rr * 2 + 1];
                if (OUT_FP32) {
                    if (Res) {
                        float2 rv = *(const float2*)&Res[(size_t)r * DM_ + cg];
                        v0 += rv.x; v1 += rv.y;
                    }
                    *(float2*)&Cf[(size_t)r * DM_ + cg] = make_float2(v0, v1);
                } else {
                    __nv_bfloat16 h0, h1, l0, l1;
                    split_bf16(v0, h0, l0); split_bf16(v1, h1, l1);
                    *(__nv_bfloat162*)&Ch[(size_t)r * DM_ + cg] = __halves2bfloat162(h0, h1);
                    *(__nv_bfloat162*)&Cl[(size_t)r * DM_ + cg] = __halves2bfloat162(l0, l1);
                }
            }
        }
    }
}

// =====================================================================
// Scores from pre-split Q/K: attn[bh,q,k] = masked ? -1e9 : (q.k)/8
// Block 128q x 128k, 8 warps (4x2), warp 32q x 64k, d=64 resident.
// =====================================================================
#define SC_QH 0
#define SC_QL (128 * PADK * 2)
#define SC_KH (2 * 128 * PADK * 2)
#define SC_KL (3 * 128 * PADK * 2)
#define SC_SMEM_BYTES (4 * 128 * PADK * 2)   // 73728

__global__ __launch_bounds__(256) void scores_mma(
    const __nv_bfloat16* __restrict__ Qh, const __nv_bfloat16* __restrict__ Ql,
    const __nv_bfloat16* __restrict__ Kh, const __nv_bfloat16* __restrict__ Kl,
    const unsigned char* __restrict__ mask_u8, float* __restrict__ attn)
{
    extern __shared__ __align__(16) char dsm[];
    const uint32_t sbase = (uint32_t)__cvta_generic_to_shared(dsm);

    const int bh = blockIdx.z;
    const int b  = bh >> 4;
    const int h  = bh & 15;
    const int q0 = blockIdx.y * 128;
    const int k0 = blockIdx.x * 128;
    const int tid  = threadIdx.x;
    const int lane = tid & 31;
    const int warp = tid >> 5;
    const int wm   = warp & 3;
    const int wn   = warp >> 2;
    const int mode = g_maskmode;

    // load 4 tiles (128 x 64 bf16 each) straight to smem
    const int r = tid >> 3, c8 = (tid & 7) * 8;
#pragma unroll
    for (int i = 0; i < 4; ++i) {
        size_t qoff = (size_t)(b * S_ + q0 + r + i * 32) * DM_ + h * DK_ + c8;
        size_t koff = (size_t)(b * S_ + k0 + r + i * 32) * DM_ + h * DK_ + c8;
        uint32_t eo = (uint32_t)((r + i * 32) * PADK + c8) * 2;
        *(uint4*)(dsm + SC_QH + eo) = *(const uint4*)&Qh[qoff];
        *(uint4*)(dsm + SC_QL + eo) = *(const uint4*)&Ql[qoff];
        *(uint4*)(dsm + SC_KH + eo) = *(const uint4*)&Kh[koff];
        *(uint4*)(dsm + SC_KL + eo) = *(const uint4*)&Kl[koff];
    }
    __syncthreads();

    float acc[2][8][4];
#pragma unroll
    for (int i = 0; i < 2; i++)
#pragma unroll
        for (int j = 0; j < 8; j++)
#pragma unroll
            for (int k = 0; k < 4; k++) acc[i][j][k] = 0.f;

    uint32_t aoff[2];
#pragma unroll
    for (int mi = 0; mi < 2; ++mi)
        aoff[mi] = (uint32_t)((wm * 32 + mi * 16 + (lane & 15)) * PADK + (lane >> 4) * 8);
    const uint32_t bbase = (uint32_t)((wn * 64 + (lane >> 4) * 8 + (lane & 7)) * PADK
                                      + ((lane >> 3) & 1) * 8);

#pragma unroll
    for (int ks = 0; ks < 4; ++ks) {
        uint32_t ah[2][4], al[2][4], bh[4][4], bl[4][4];
#pragma unroll
        for (int mi = 0; mi < 2; ++mi) {
            uint32_t eo = (aoff[mi] + ks * 16) * 2;
            ldsm_x4(ah[mi], sbase + SC_QH + eo);
            ldsm_x4(al[mi], sbase + SC_QL + eo);
        }
#pragma unroll
        for (int j = 0; j < 4; ++j) {
            uint32_t eo = (bbase + j * 16 * PADK + ks * 16) * 2;
            ldsm_x4(bh[j], sbase + SC_KH + eo);
            ldsm_x4(bl[j], sbase + SC_KL + eo);
        }
#pragma unroll
        for (int mi = 0; mi < 2; ++mi) {
#pragma unroll
            for (int nj = 0; nj < 8; ++nj) {
                const uint32_t* bhp = &bh[nj >> 1][(nj & 1) * 2];
                const uint32_t* blp = &bl[nj >> 1][(nj & 1) * 2];
                mma_bf16(acc[mi][nj], ah[mi], bhp);
                mma_bf16(acc[mi][nj], ah[mi], blp);
                mma_bf16(acc[mi][nj], al[mi], bhp);
            }
        }
    }

    const int*   mask_i32 = (const int*)mask_u8;
    const float* mask_f32 = (const float*)mask_u8;
#pragma unroll
    for (int mi = 0; mi < 2; ++mi) {
#pragma unroll
        for (int nj = 0; nj < 8; ++nj) {
            int qg = q0 + wm * 32 + mi * 16 + (lane >> 2);
            int kg = k0 + wn * 64 + nj * 8 + (lane & 3) * 2;
#pragma unroll
            for (int rr = 0; rr < 2; ++rr) {
                int qr = qg + rr * 8;
                float s0 = acc[mi][nj][rr * 2 + 0] * 0.125f;
                float s1 = acc[mi][nj][rr * 2 + 1] * 0.125f;
                size_t midx = ((size_t)b * S_ + qr) * S_ + kg;
                bool m0, m1;
                if (mode == 1) {
                    int2 mv = *(const int2*)&mask_i32[midx];
                    m0 = mv.x != 0; m1 = mv.y != 0;
                } else if (mode == 0) {
                    m0 = mask_u8[midx] != 0; m1 = mask_u8[midx + 1] != 0;
                } else {
                    float2 mv = *(const float2*)&mask_f32[midx];
                    m0 = mv.x != 0.0f; m1 = mv.y != 0.0f;
                }
                float2 v = make_float2(m0 ? -1e9f : s0, m1 ? -1e9f : s1);
                *(float2*)&attn[((size_t)bh * S_ + qr) * S_ + kg] = v;
            }
        }
    }
}

// =====================================================================
// Row softmax over 2048: contiguous float4, FMA-pipe exp
// =====================================================================
__global__ __launch_bounds__(256) void softmax_kernel(float* __restrict__ attn)
{
    const int tid = threadIdx.x;
    float* p = attn + (size_t)blockIdx.x * S_ + tid * 8;
    const int warp = tid >> 5, lane = tid & 31;
    __shared__ float red[8];

    float4 va = *(const float4*)p;
    float4 vb = *(const float4*)(p + 4);
    float v[8] = {va.x, va.y, va.z, va.w, vb.x, vb.y, vb.z, vb.w};

    float m = v[0];
#pragma unroll
    for (int j = 1; j < 8; j++) m = fmaxf(m, v[j]);
#pragma unroll
    for (int o = 16; o > 0; o >>= 1) m = fmaxf(m, __shfl_xor_sync(0xffffffffu, m, o));
    if (lane == 0) red[warp] = m;
    __syncthreads();
    if (tid == 0) {
        float t = red[0];
#pragma unroll
        for (int w = 1; w < 8; w++) t = fmaxf(t, red[w]);
        red[0] = t;
    }
    __syncthreads();
    m = red[0];

    float s = 0.f;
#pragma unroll
    for (int j = 0; j < 8; j++) { v[j] = fexp(v[j] - m); s += v[j]; }
#pragma unroll
    for (int o = 16; o > 0; o >>= 1) s += __shfl_xor_sync(0xffffffffu, s, o);
    __syncthreads();
    if (lane == 0) red[warp] = s;
    __syncthreads();
    if (tid == 0) {
        float t = 0.f;
#pragma unroll
        for (int w = 0; w < 8; w++) t += red[w];
        red[0] = t;
    }
    __syncthreads();
    float inv = 1.0f / red[0];

    *(float4*)p       = make_float4(v[0] * inv, v[1] * inv, v[2] * inv, v[3] * inv);
    *(float4*)(p + 4) = make_float4(v[4] * inv, v[5] * inv, v[6] * inv, v[7] * inv);
}

// =====================================================================
// Context: per bh, ctx[2048,64] = attn[2048,2048] @ V[2048,64]
// attn fp32 split inline (read-once); V pre-split; ctx emitted hi/lo bf16.
// grid (1, 16, 32)
// =====================================================================
__global__ __launch_bounds__(256) void ctx_mma(
    const float* __restrict__ attnp,
    const __nv_bfloat16* __restrict__ Vh, const __nv_bfloat16* __restrict__ Vl,
    __nv_bfloat16* __restrict__ Ch, __nv_bfloat16* __restrict__ Cl)
{
    extern __shared__ __align__(16) char dsm[];
    const uint32_t sbase = (uint32_t)__cvta_generic_to_shared(dsm);

    const int bh = blockIdx.z;
    const int b  = bh >> 4;
    const int h  = bh & 15;
    const int row0 = blockIdx.y * 128;
    const int tid  = threadIdx.x;
    const int lane = tid & 31;
    const int warp = tid >> 5;
    const int wm   = warp & 3;
    const int wn   = warp >> 2;

    const float* A = attnp + (size_t)bh * S_ * S_;
    const size_t voff0 = (size_t)b * S_ * DM_ + h * DK_;

    float acc[2][4][4];
#pragma unroll
    for (int i = 0; i < 2; i++)
#pragma unroll
        for (int j = 0; j < 4; j++)
#pragma unroll
            for (int k = 0; k < 4; k++) acc[i][j][k] = 0.f;

    uint32_t aoff[2], boff[2];
#pragma unroll
    for (int mi = 0; mi < 2; ++mi)
        aoff[mi] = (uint32_t)((wm * 32 + mi * 16 + (lane & 15)) * PADK + (lane >> 4) * 8);
#pragma unroll
    for (int njp = 0; njp < 2; ++njp)
        boff[njp] = (uint32_t)((((lane >> 3) & 1) * 8 + (lane & 7)) * PADK
                               + wn * 32 + njp * 16 + (lane >> 4) * 8);

    const int br = tid >> 3, bc8 = (tid & 7) * 8;

    for (int c = 0; c < S_ / 64; ++c) {
        const int k0 = c * 64;

        float4 av[8];
#pragma unroll
        for (int i = 0; i < 8; ++i) {
            int idx = tid + i * 256;
            int r  = idx >> 4;
            int kc = (idx & 15) * 4;
            av[i] = *(const float4*)&A[(size_t)(row0 + r) * S_ + k0 + kc];
        }
        uint4 bh4[2], bl4[2];
#pragma unroll
        for (int i = 0; i < 2; ++i) {
            size_t off = voff0 + (size_t)(k0 + br + i * 32) * DM_ + bc8;
            bh4[i] = *(const uint4*)&Vh[off];
            bl4[i] = *(const uint4*)&Vl[off];
        }

        if (c > 0) __syncthreads();

#pragma unroll
        for (int i = 0; i < 8; ++i) {
            int idx = tid + i * 256;
            int r  = idx >> 4;
            int kc = (idx & 15) * 4;
            uint32_t eo = (uint32_t)(r * PADK + kc) * 2;
            __nv_bfloat16 h0, h1, h2, h3, l0, l1, l2, l3;
            split_bf16(av[i].x, h0, l0); split_bf16(av[i].y, h1, l1);
            split_bf16(av[i].z, h2, l2); split_bf16(av[i].w, h3, l3);
            *(__nv_bfloat162*)(dsm + SM_AH + eo)     = __halves2bfloat162(h0, h1);
            *(__nv_bfloat162*)(dsm + SM_AH + eo + 4) = __halves2bfloat162(h2, h3);
            *(__nv_bfloat162*)(dsm + SM_AL + eo)     = __halves2bfloat162(l0, l1);
            *(__nv_bfloat162*)(dsm + SM_AL + eo + 4) = __halves2bfloat162(l2, l3);
        }
#pragma unroll
        for (int i = 0; i < 2; ++i) {
            uint32_t eo = (uint32_t)((br + i * 32) * PADK + bc8) * 2;
            *(uint4*)(dsm + SM_BH + eo) = bh4[i];
            *(uint4*)(dsm + SM_BL + eo) = bl4[i];
        }
        __syncthreads();

#pragma unroll
        for (int ks = 0; ks < 4; ++ks) {
            uint32_t ah[2][4], al[2][4], bh[2][4], bl[2][4];
#pragma unroll
            for (int mi = 0; mi < 2; ++mi) {
                uint32_t eo = (aoff[mi] + ks * 16) * 2;
                ldsm_x4(ah[mi], sbase + SM_AH + eo);
                ldsm_x4(al[mi], sbase + SM_AL + eo);
            }
#pragma unroll
            for (int njp = 0; njp < 2; ++njp) {
                uint32_t eo = (boff[njp] + ks * 16 * PADK) * 2;
                ldsm_x4t(bh[njp], sbase + SM_BH + eo);
                ldsm_x4t(bl[njp], sbase + SM_BL + eo);
            }
#pragma unroll
            for (int mi = 0; mi < 2; ++mi) {
#pragma unroll
                for (int nj = 0; nj < 4; ++nj) {
                    const uint32_t* bhp = &bh[nj >> 1][(nj & 1) * 2];
                    const uint32_t* blp = &bl[nj >> 1][(nj & 1) * 2];
                    mma_bf16(acc[mi][nj], ah[mi], bhp);
                    mma_bf16(acc[mi][nj], ah[mi], blp);
                    mma_bf16(acc[mi][nj], al[mi], bhp);
                }
            }
        }
    }

#pragma unroll
    for (int mi = 0; mi < 2; ++mi) {
#pragma unroll
        for (int nj = 0; nj < 4; ++nj) {
            int rg = row0 + wm * 32 + mi * 16 + (lane >> 2);
            int cg = wn * 32 + nj * 8 + (lane & 3) * 2;
#pragma unroll
            for (int rr = 0; rr < 2; ++rr) {
                int r = rg + rr * 8;
                float v0 = acc[mi][nj][rr * 2 + 0];
                float v1 = acc[mi][nj][rr * 2 + 1];
                __nv_bfloat16 h0, h1, l0, l1;
                split_bf16(v0, h0, l0); split_bf16(v1, h1, l1);
                size_t o = (size_t)(b * S_ + r) * DM_ + h * DK_ + cg;
                *(__nv_bfloat162*)&Ch[o] = __halves2bfloat162(h0, h1);
                *(__nv_bfloat162*)&Cl[o] = __halves2bfloat162(l0, l1);
            }
        }
    }
}

// =====================================================================
// LayerNorm (unchanged)
// =====================================================================
__global__ __launch_bounds__(256) void ln_kernel(
    const float* __restrict__ y, float* __restrict__ out)
{
    const int tid = threadIdx.x;
    const float* p = y + (size_t)blockIdx.x * DM_;
    float* o = out + (size_t)blockIdx.x * DM_;
    const int warp = tid >> 5, lane = tid & 31;
    __shared__ float red[8];

    float v[4];
#pragma unroll
    for (int j = 0; j < 4; j++) v[j] = p[tid + j * 256];

    float s = v[0] + v[1] + v[2] + v[3];
#pragma unroll
    for (int o2 = 16; o2 > 0; o2 >>= 1) s += __shfl_xor_sync(0xffffffffu, s, o2);
    if (lane == 0) red[warp] = s;
    __syncthreads();
    if (tid == 0) {
        float t = 0.f;
#pragma unroll
        for (int w = 0; w < 8; w++) t += red[w];
        red[0] = t;
    }
    __syncthreads();
    float mu = red[0] * (1.0f / DM_);

    float sq = 0.f;
#pragma unroll
    for (int j = 0; j < 4; j++) { float d = v[j] - mu; sq += d * d; }
#pragma unroll
    for (int o2 = 16; o2 > 0; o2 >>= 1) sq += __shfl_xor_sync(0xffffffffu, sq, o2);
    __syncthreads();
    if (lane == 0) red[warp] = sq;
    __syncthreads();
    if (tid == 0) {
        float t = 0.f;
#pragma unroll
        for (int w = 0; w < 8; w++) t += red[w];
        red[0] = t;
    }
    __syncthreads();
    float inv = rsqrtf(red[0] * (1.0f / DM_) + 1e-5f);

#pragma unroll
    for (int j = 0; j < 4; j++) o[tid + j * 256] = (v[j] - mu) * inv;
}

// =====================================================================
// Launch
// =====================================================================
extern "C" void kernel_launch(void* const* d_in, const int* in_sizes, int n_in,
                              void* d_out, int out_size)
{
    const float* inQ = (const float*)d_in[0];
    const float* inK = (const float*)d_in[1];
    const float* inV = (const float*)d_in[2];
    const unsigned char* mask = (const unsigned char*)d_in[3];
    const float* WQ = (const float*)d_in[4];
    const float* WK = (const float*)d_in[5];
    const float* WV = (const float*)d_in[6];
    const float* WO = (const float*)d_in[7];
    float* out = (float*)d_out;

    float *Yp, *Ap;
    __nv_bfloat16 *Ah, *Al, *Wh, *Wl, *Qh, *Ql, *Kh, *Kl, *Vh, *Vl;
    cudaGetSymbolAddress((void**)&Yp, g_y);
    cudaGetSymbolAddress((void**)&Ap, g_attn);
    cudaGetSymbolAddress((void**)&Ah, g_Ah);
    cudaGetSymbolAddress((void**)&Al, g_Al);
    cudaGetSymbolAddress((void**)&Wh, g_Wh);
    cudaGetSymbolAddress((void**)&Wl, g_Wl);
    cudaGetSymbolAddress((void**)&Qh, g_Qh);
    cudaGetSymbolAddress((void**)&Ql, g_Ql);
    cudaGetSymbolAddress((void**)&Kh, g_Kh);
    cudaGetSymbolAddress((void**)&Kl, g_Kl);
    cudaGetSymbolAddress((void**)&Vh, g_Vh);
    cudaGetSymbolAddress((void**)&Vl, g_Vl);

    float* attn = ((long long)out_size >= OUT_ELEMS + ATTN_ELEMS) ? (out + OUT_ELEMS) : Ap;

    cudaFuncSetAttribute(gemm_bf16<true>, cudaFuncAttributeMaxDynamicSharedMemorySize,
                         MMA_SMEM_BYTES);
    cudaFuncSetAttribute(gemm_bf16<false>, cudaFuncAttributeMaxDynamicSharedMemorySize,
                         MMA_SMEM_BYTES);
    cudaFuncSetAttribute(ctx_mma, cudaFuncAttributeMaxDynamicSharedMemorySize,
                         MMA_SMEM_BYTES);
    cudaFuncSetAttribute(scores_mma, cudaFuncAttributeMaxDynamicSharedMemorySize,
                         SC_SMEM_BYTES);

    detect_mask_kernel<<<1, 256>>>(mask);

    const int inBlocks = (M_ * DM_) / (256 * 8);   // 2048
    const int wBlocks  = (DM_ * DM_) / (256 * 8);  // 512
    dim3 proj_grid(DM_ / 64, M_ / 128);            // (16, 32)

    conv_split<<<inBlocks, 256>>>(inQ, Ah, Al);
    conv_split<<<wBlocks, 256>>>(WQ, Wh, Wl);
    gemm_bf16<false><<<proj_grid, 256, MMA_SMEM_BYTES>>>(Ah, Al, Wh, Wl, nullptr, nullptr, Qh, Ql);

    conv_split<<<inBlocks, 256>>>(inK, Ah, Al);
    conv_split<<<wBlocks, 256>>>(WK, Wh, Wl);
    gemm_bf16<false><<<proj_grid, 256, MMA_SMEM_BYTES>>>(Ah, Al, Wh, Wl, nullptr, nullptr, Kh, Kl);

    conv_split<<<inBlocks, 256>>>(inV, Ah, Al);
    conv_split<<<wBlocks, 256>>>(WV, Wh, Wl);
    gemm_bf16<false><<<proj_grid, 256, MMA_SMEM_BYTES>>>(Ah, Al, Wh, Wl, nullptr, nullptr, Vh, Vl);

    scores_mma<<<dim3(S_ / 128, S_ / 128, B_ * H_), 256, SC_SMEM_BYTES>>>(Qh, Ql, Kh, Kl, mask, attn);
    softmax_kernel<<<B_ * H_ * S_, 256>>>(attn);
    ctx_mma<<<dim3(1, S_ / 128, B_ * H_), 256, MMA_SMEM_BYTES>>>(attn, Vh, Vl, Ah, Al);

    conv_split<<<wBlocks, 256>>>(WO, Wh, Wl);
    gemm_bf16<true><<<proj_grid, 256, MMA_SMEM_BYTES>>>(Ah, Al, Wh, Wl, inQ, Yp, nullptr, nullptr);
    ln_kernel<<<M_, 256>>>(Yp, out);
}